// round 2
// baseline (speedup 1.0000x reference)
#include <cuda_runtime.h>
#include <math.h>

// ---------------------------------------------------------------------------
// Problem constants (RPN: B=16, C=512, H=38, W=50)
// ---------------------------------------------------------------------------
#define BATCH   16
#define CHAN    512
#define FH      38
#define FW      50
#define HW      1900            // FH*FW
#define NPOS    30400           // BATCH*HW
#define NANCH   17100           // HW*9
#define KCONV   4608            // 512*3*3
#define PRE_N   6000
#define POST_N  300
#define IMGH    608.0f
#define IMGW    800.0f
#define MINSZ   16.0f
#define NMS_T   0.7f

#define NEG_INF (__int_as_float(0xff800000))

// ---------------------------------------------------------------------------
// Scratch (device globals; no allocations allowed)
// ---------------------------------------------------------------------------
__device__ float g_shared[(size_t)BATCH * CHAN * HW];   // conv output (~62 MB)
__device__ float g_heads[54 * NPOS];                    // 18 cls + 36 reg
__device__ float g_scores[BATCH * NANCH];
__device__ float g_boxes[(size_t)BATCH * NANCH * 4];
__device__ unsigned int g_thr[BATCH];

__device__ __forceinline__ unsigned int fkey(float f) {
    unsigned int u = __float_as_uint(f);
    return (u & 0x80000000u) ? ~u : (u | 0x80000000u);
}

// ---------------------------------------------------------------------------
// Kernel 1: 3x3 conv + ReLU as implicit GEMM
//   C[co][p] = sum_k W[co][k] * patch(k, p),  k = ci*9 + r*3 + s
//   BM=128 (co), BN=128 (pos), BK=8, 256 threads, 8x8 per thread
// ---------------------------------------------------------------------------
__global__ __launch_bounds__(256, 2)
void conv3x3_relu_kernel(const float* __restrict__ X,
                         const float* __restrict__ W,
                         const float* __restrict__ bias)
{
    __shared__ float As[8][128];
    __shared__ float Bs[8][128];

    const int tid = threadIdx.x;
    const int tx = tid & 15;          // pos sub-tile
    const int ty = tid >> 4;          // co  sub-tile
    const int n0 = blockIdx.x * 128;  // pos tile origin
    const int m0 = blockIdx.y * 128;  // co  tile origin

    // per-thread position for B loading (fixed across K loop)
    const int nl = tid & 127;
    const int pL = n0 + nl;
    const bool pOK = (pL < NPOS);
    const int pc = pOK ? pL : 0;
    const int bL = pc / HW;
    const int rL = pc - bL * HW;
    const int yL = rL / FW;
    const int xL = rL - yL * FW;
    const float* Xb = X + (size_t)bL * CHAN * HW;

    const int aRow = tid >> 1;          // 0..127
    const int aK   = (tid & 1) * 4;     // 0 or 4
    const int kkB0 = (tid >> 7) * 4;    // 0 or 4

    float acc[8][8];
#pragma unroll
    for (int i = 0; i < 8; i++)
#pragma unroll
        for (int j = 0; j < 8; j++) acc[i][j] = 0.f;

    const float* Wrow = W + (size_t)(m0 + aRow) * KCONV + aK;

    for (int k0 = 0; k0 < KCONV; k0 += 8) {
        // global -> regs
        float4 av = *reinterpret_cast<const float4*>(Wrow + k0);
        float bv[4];
#pragma unroll
        for (int q = 0; q < 4; q++) {
            int k  = k0 + kkB0 + q;
            int ci = k / 9;
            int t9 = k - ci * 9;
            int r  = t9 / 3;
            int s  = t9 - r * 3;
            int iy = yL + r - 1;
            int ix = xL + s - 1;
            float v = 0.f;
            if (pOK && (unsigned)iy < (unsigned)FH && (unsigned)ix < (unsigned)FW)
                v = Xb[(ci * FH + iy) * FW + ix];
            bv[q] = v;
        }
        __syncthreads();
        As[aK + 0][aRow] = av.x;
        As[aK + 1][aRow] = av.y;
        As[aK + 2][aRow] = av.z;
        As[aK + 3][aRow] = av.w;
#pragma unroll
        for (int q = 0; q < 4; q++) Bs[kkB0 + q][nl] = bv[q];
        __syncthreads();

#pragma unroll
        for (int kk = 0; kk < 8; kk++) {
            float a[8], b[8];
            *reinterpret_cast<float4*>(&a[0]) = *reinterpret_cast<float4*>(&As[kk][ty * 8]);
            *reinterpret_cast<float4*>(&a[4]) = *reinterpret_cast<float4*>(&As[kk][ty * 8 + 4]);
            *reinterpret_cast<float4*>(&b[0]) = *reinterpret_cast<float4*>(&Bs[kk][tx * 8]);
            *reinterpret_cast<float4*>(&b[4]) = *reinterpret_cast<float4*>(&Bs[kk][tx * 8 + 4]);
#pragma unroll
            for (int i = 0; i < 8; i++)
#pragma unroll
                for (int j = 0; j < 8; j++)
                    acc[i][j] = fmaf(a[i], b[j], acc[i][j]);
        }
    }

    // epilogue: bias + ReLU, store NCHW
#pragma unroll
    for (int i = 0; i < 8; i++) {
        int co = m0 + ty * 8 + i;
        float bb = bias[co];
#pragma unroll
        for (int j = 0; j < 8; j++) {
            int p = n0 + tx * 8 + j;
            if (p < NPOS) {
                int b  = p / HW;
                int rr = p - b * HW;
                float v = acc[i][j] + bb;
                g_shared[((size_t)b * CHAN + co) * HW + rr] = v > 0.f ? v : 0.f;
            }
        }
    }
}

// ---------------------------------------------------------------------------
// Kernel 2: 1x1 heads as GEMM  heads[o][p] (o<18: cls, 18..53: reg)
//   M=54 (padded 64), N=30400, K=512.  BM=64, BN=64, BK=16, 256 thr, 4x4.
// ---------------------------------------------------------------------------
__global__ __launch_bounds__(256)
void head_gemm_kernel(const float* __restrict__ clsW, const float* __restrict__ clsB,
                      const float* __restrict__ regW, const float* __restrict__ regB)
{
    __shared__ float As[16][64];
    __shared__ float Bs[16][64];

    const int tid = threadIdx.x;
    const int tx = tid & 15;
    const int ty = tid >> 4;
    const int n0 = blockIdx.x * 64;

    const int nl = tid & 63;
    const int p  = n0 + nl;          // NPOS % 64 == 0, always valid
    const int bL = p / HW;
    const int rL = p - bL * HW;
    const float* Sb = g_shared + (size_t)bL * CHAN * HW + rL;

    const int aRow = tid >> 2;       // 0..63
    const int aK   = (tid & 3) * 4;
    const int kk0  = (tid >> 6) * 4; // 0,4,8,12

    float acc[4][4];
#pragma unroll
    for (int i = 0; i < 4; i++)
#pragma unroll
        for (int j = 0; j < 4; j++) acc[i][j] = 0.f;

    for (int k0 = 0; k0 < CHAN; k0 += 16) {
        float4 av;
        if (aRow < 18)      av = *reinterpret_cast<const float4*>(&clsW[aRow * CHAN + k0 + aK]);
        else if (aRow < 54) av = *reinterpret_cast<const float4*>(&regW[(aRow - 18) * CHAN + k0 + aK]);
        else                av = make_float4(0.f, 0.f, 0.f, 0.f);
        float bv[4];
#pragma unroll
        for (int q = 0; q < 4; q++)
            bv[q] = Sb[(size_t)(k0 + kk0 + q) * HW];
        __syncthreads();
        As[aK + 0][aRow] = av.x;
        As[aK + 1][aRow] = av.y;
        As[aK + 2][aRow] = av.z;
        As[aK + 3][aRow] = av.w;
#pragma unroll
        for (int q = 0; q < 4; q++) Bs[kk0 + q][nl] = bv[q];
        __syncthreads();

#pragma unroll
        for (int kk = 0; kk < 16; kk++) {
            float a[4], b[4];
            *reinterpret_cast<float4*>(&a[0]) = *reinterpret_cast<float4*>(&As[kk][ty * 4]);
            *reinterpret_cast<float4*>(&b[0]) = *reinterpret_cast<float4*>(&Bs[kk][tx * 4]);
#pragma unroll
            for (int i = 0; i < 4; i++)
#pragma unroll
                for (int j = 0; j < 4; j++)
                    acc[i][j] = fmaf(a[i], b[j], acc[i][j]);
        }
        __syncthreads();
    }

#pragma unroll
    for (int i = 0; i < 4; i++) {
        int o = ty * 4 + i;
        if (o < 54) {
            float bb = (o < 18) ? clsB[o] : regB[o - 18];
#pragma unroll
            for (int j = 0; j < 4; j++)
                g_heads[o * NPOS + n0 + tx * 4 + j] = acc[i][j] + bb;
        }
    }
}

// ---------------------------------------------------------------------------
// Kernel 3: softmax over 18 cls channels, anchor decode, clip, min-size
// One thread per spatial position (9 anchors each).
// ---------------------------------------------------------------------------
__global__ void decode_kernel()
{
    int p = blockIdx.x * 256 + threadIdx.x;
    if (p >= NPOS) return;
    int b  = p / HW;
    int rr = p - b * HW;
    int y  = rr / FW;
    int x  = rr - y * FW;

    float c[18];
    float mx = -1e30f;
#pragma unroll
    for (int o = 0; o < 18; o++) {
        c[o] = g_heads[o * NPOS + p];
        mx = fmaxf(mx, c[o]);
    }
    float sum = 0.f;
#pragma unroll
    for (int o = 0; o < 18; o++) {
        c[o] = expf(c[o] - mx);
        sum += c[o];
    }

    const float ys = (float)(y * 16);
    const float xs = (float)(x * 16);

    for (int a = 0; a < 9; a++) {
        int ri = a / 3, si = a - ri * 3;
        double ratio = (ri == 0) ? 0.5 : (ri == 1 ? 1.0 : 2.0);
        double scale = (si == 0) ? 8.0 : (si == 1 ? 16.0 : 32.0);
        double hhd = 16.0 * scale * sqrt(ratio);
        double wwd = 16.0 * scale * sqrt(1.0 / ratio);
        // base anchors computed in double then cast, matching numpy
        float b0 = (float)(8.0 - hhd / 2.0);
        float b1 = (float)(8.0 - wwd / 2.0);
        float b2 = (float)(8.0 + hhd / 2.0);
        float b3 = (float)(8.0 + wwd / 2.0);
        // shift-then-difference, matching reference arithmetic order
        float a0 = ys + b0, a1 = xs + b1, a2 = ys + b2, a3 = xs + b3;
        float ah = a2 - a0, aw = a3 - a1;
        float acy = a0 + 0.5f * ah;
        float acx = a1 + 0.5f * aw;

        float dy = g_heads[(18 + a * 4 + 0) * NPOS + p];
        float dx = g_heads[(18 + a * 4 + 1) * NPOS + p];
        float dh = g_heads[(18 + a * 4 + 2) * NPOS + p];
        float dw = g_heads[(18 + a * 4 + 3) * NPOS + p];

        float cy = dy * ah + acy;
        float cx = dx * aw + acx;
        float bh = expf(dh) * ah;
        float bw = expf(dw) * aw;

        float y1 = fminf(fmaxf(cy - 0.5f * bh, 0.f), IMGH);
        float x1 = fminf(fmaxf(cx - 0.5f * bw, 0.f), IMGW);
        float y2 = fminf(fmaxf(cy + 0.5f * bh, 0.f), IMGH);
        float x2 = fminf(fmaxf(cx + 0.5f * bw, 0.f), IMGW);

        bool keep = (y2 - y1 >= MINSZ) && (x2 - x1 >= MINSZ);
        float fg = c[2 * a + 1] / sum;
        float sc = keep ? fg : NEG_INF;

        int n = rr * 9 + a;
        size_t bi = ((size_t)b * NANCH + n) * 4;
        g_boxes[bi + 0] = y1;
        g_boxes[bi + 1] = x1;
        g_boxes[bi + 2] = y2;
        g_boxes[bi + 3] = x2;
        g_scores[b * NANCH + n] = sc;
    }
}

// ---------------------------------------------------------------------------
// Kernel 4: per-image 6000th-largest score key (binary search on uint keys)
// ---------------------------------------------------------------------------
__global__ __launch_bounds__(1024)
void thresh_kernel()
{
    extern __shared__ unsigned int sk[];   // NANCH keys
    __shared__ int s_cnt;
    __shared__ int s_warp[32];

    const int img = blockIdx.x;
    const int tid = threadIdx.x;
    const int lane = tid & 31, wrp = tid >> 5;
    const float* sc = g_scores + img * NANCH;

    for (int i = tid; i < NANCH; i += 1024) sk[i] = fkey(sc[i]);
    __syncthreads();

    unsigned int lo = 0u, hi = 0xFFFFFFFFu;
    while (lo < hi) {
        unsigned int mid = (unsigned int)(((unsigned long long)lo + hi + 1ull) >> 1);
        int c = 0;
        for (int i = tid; i < NANCH; i += 1024) c += (sk[i] >= mid);
#pragma unroll
        for (int off = 16; off; off >>= 1) c += __shfl_down_sync(0xFFFFFFFFu, c, off);
        if (lane == 0) s_warp[wrp] = c;
        __syncthreads();
        if (tid == 0) {
            int t = 0;
            for (int q = 0; q < 32; q++) t += s_warp[q];
            s_cnt = t;
        }
        __syncthreads();
        int total = s_cnt;
        __syncthreads();
        if (total >= PRE_N) lo = mid; else hi = mid - 1;
    }
    if (tid == 0) g_thr[img] = lo;
}

// ---------------------------------------------------------------------------
// Kernel 5: greedy NMS (300 fixed steps) per image, candidates in smem
// ---------------------------------------------------------------------------
__global__ __launch_bounds__(1024)
void nms_kernel(float* __restrict__ out)
{
    extern __shared__ float sm[];
    float* sS  = sm;
    float* sY1 = sm + PRE_N;
    float* sX1 = sm + 2 * PRE_N;
    float* sY2 = sm + 3 * PRE_N;
    float* sX2 = sm + 4 * PRE_N;
    float* sA  = sm + 5 * PRE_N;

    __shared__ int s_warpOff[32];
    __shared__ unsigned long long s_wbest[32];
    __shared__ int s_cnt;
    __shared__ float s_wb[5];     // y1 x1 y2 x2 area
    __shared__ int s_done;

    const int img = blockIdx.x;
    const int tid = threadIdx.x;
    const int lane = tid & 31, wrp = tid >> 5;
    const unsigned int T = g_thr[img];
    const float* sc = g_scores + img * NANCH;
    const float* bx = g_boxes + (size_t)img * NANCH * 4;
    float* outImg = out + img * POST_N * 5;

    // ---- order-preserving compaction of {finite && key >= T} ----
    const int CHK = (NANCH + 1023) / 1024;        // 17
    const int i0 = tid * CHK;
    const int i1 = min(i0 + CHK, NANCH);
    int c = 0;
    for (int i = i0; i < i1; i++) {
        float s = sc[i];
        if (s != NEG_INF && fkey(s) >= T) c++;
    }
    int incl = c;
#pragma unroll
    for (int off = 1; off < 32; off <<= 1) {
        int nv = __shfl_up_sync(0xFFFFFFFFu, incl, off);
        if (lane >= off) incl += nv;
    }
    if (lane == 31) s_warpOff[wrp] = incl;
    __syncthreads();
    if (wrp == 0) {
        int t = s_warpOff[lane];
        int ti = t;
#pragma unroll
        for (int off = 1; off < 32; off <<= 1) {
            int nv = __shfl_up_sync(0xFFFFFFFFu, ti, off);
            if (lane >= off) ti += nv;
        }
        s_warpOff[lane] = ti - t;                 // exclusive warp offsets
        if (lane == 31) s_cnt = min(ti, PRE_N);
    }
    __syncthreads();
    int pos = s_warpOff[wrp] + (incl - c);
    for (int i = i0; i < i1; i++) {
        float s = sc[i];
        if (s != NEG_INF && fkey(s) >= T) {
            if (pos < PRE_N) {
                float y1 = bx[(size_t)i * 4 + 0];
                float x1 = bx[(size_t)i * 4 + 1];
                float y2 = bx[(size_t)i * 4 + 2];
                float x2 = bx[(size_t)i * 4 + 3];
                sS[pos] = s;
                sY1[pos] = y1; sX1[pos] = x1; sY2[pos] = y2; sX2[pos] = x2;
                sA[pos] = (y2 - y1) * (x2 - x1);
            }
            pos++;
        }
    }
    __syncthreads();
    const int cnt = s_cnt;

    // ---- 300 greedy steps ----
    for (int j = 0; j < POST_N; j++) {
        unsigned long long best = 0ull;
        for (int i = tid; i < cnt; i += 1024) {
            unsigned long long k =
                ((unsigned long long)fkey(sS[i]) << 32) |
                (unsigned long long)(0xFFFFFFFFu - (unsigned int)i);
            best = max(best, k);
        }
#pragma unroll
        for (int off = 16; off; off >>= 1) {
            unsigned long long o = __shfl_down_sync(0xFFFFFFFFu, best, off);
            best = max(best, o);
        }
        if (lane == 0) s_wbest[wrp] = best;
        __syncthreads();
        if (tid == 0) {
            unsigned long long bb = s_wbest[0];
            for (int q = 1; q < 32; q++) bb = max(bb, s_wbest[q]);
            int bi = (int)(0xFFFFFFFFu - (unsigned int)(bb & 0xFFFFFFFFull));
            float s = (cnt > 0) ? sS[bi] : NEG_INF;
            if (cnt == 0 || s == NEG_INF) {
                s_done = 1;
            } else {
                s_done = 0;
                s_wb[0] = sY1[bi]; s_wb[1] = sX1[bi];
                s_wb[2] = sY2[bi]; s_wb[3] = sX2[bi];
                s_wb[4] = sA[bi];
                outImg[j * 5 + 0] = sY1[bi];
                outImg[j * 5 + 1] = sX1[bi];
                outImg[j * 5 + 2] = sY2[bi];
                outImg[j * 5 + 3] = sX2[bi];
                outImg[j * 5 + 4] = s;
            }
        }
        __syncthreads();
        if (s_done) {
            for (int z = j * 5 + tid; z < POST_N * 5; z += 1024) outImg[z] = 0.f;
            return;
        }
        float wy1 = s_wb[0], wx1 = s_wb[1], wy2 = s_wb[2], wx2 = s_wb[3], wa = s_wb[4];
        for (int i = tid; i < cnt; i += 1024) {
            float s = sS[i];
            if (s != NEG_INF) {
                float yy1 = fmaxf(wy1, sY1[i]);
                float xx1 = fmaxf(wx1, sX1[i]);
                float yy2 = fminf(wy2, sY2[i]);
                float xx2 = fminf(wx2, sX2[i]);
                float inter = fmaxf(yy2 - yy1, 0.f) * fmaxf(xx2 - xx1, 0.f);
                float iou = inter / (sA[i] + wa - inter + 1e-9f);
                if (iou > NMS_T) sS[i] = NEG_INF;   // also suppresses the winner (iou≈1)
            }
        }
        __syncthreads();
    }
}

// ---------------------------------------------------------------------------
// Launch
// ---------------------------------------------------------------------------
extern "C" void kernel_launch(void* const* d_in, const int* in_sizes, int n_in,
                              void* d_out, int out_size)
{
    (void)in_sizes; (void)n_in; (void)out_size;
    const float* x  = (const float*)d_in[0];
    const float* sw = (const float*)d_in[1];
    const float* sb = (const float*)d_in[2];
    const float* cw = (const float*)d_in[3];
    const float* cb = (const float*)d_in[4];
    const float* rw = (const float*)d_in[5];
    const float* rb = (const float*)d_in[6];
    float* out = (float*)d_out;

    cudaFuncSetAttribute(thresh_kernel, cudaFuncAttributeMaxDynamicSharedMemorySize,
                         NANCH * (int)sizeof(unsigned int));
    cudaFuncSetAttribute(nms_kernel, cudaFuncAttributeMaxDynamicSharedMemorySize,
                         6 * PRE_N * (int)sizeof(float));

    conv3x3_relu_kernel<<<dim3((NPOS + 127) / 128, CHAN / 128), 256>>>(x, sw, sb);
    head_gemm_kernel<<<NPOS / 64, 256>>>(cw, cb, rw, rb);
    decode_kernel<<<(NPOS + 255) / 256, 256>>>();
    thresh_kernel<<<BATCH, 1024, NANCH * sizeof(unsigned int)>>>();
    nms_kernel<<<BATCH, 1024, 6 * PRE_N * sizeof(float)>>>(out);
}